// round 15
// baseline (speedup 1.0000x reference)
#include <cuda_runtime.h>
#include <cuda_bf16.h>
#include <cuda_fp16.h>
#include <mma.h>
#include <math.h>
#include <stdint.h>

using namespace nvcuda;

// ---------------------------------------------------------------------------
// Problem constants
// ---------------------------------------------------------------------------
#define NB   64
#define TT   300
#define VV   25
#define PC   26                 // padded cols per frame
#define EMB  96
#define TVA  (TT*PC)            // 7800
#define NFB  (TT+4)             // 304
#define TVB2 7912               // B row stride (halves)
#define OUTTV (TT*VV)           // 7500

// kOutTC smem layout (bytes): warp-specialized, 1 CTA/SM
#define LDA      136
#define LDBS     232
#define OFF_A    0              // As  [96][136] fp16 = 26112
#define OFF_H0   26112          // H0  [96][136] fp16 = 26112
#define OFF_H1   52224          // H1  [96][136] fp16 = 26112
#define OFF_B    78336          // Bs  [96][232] fp16 = 44544
#define OFF_W0   122880         // Ws0 [96][104] fp16 = 19968
#define OFF_W1   142848         // Ws1 [96][104] fp16 = 19968
#define OFF_OBS  162816         // [96] f32 = 384
#define SMEM_TC  163200
#define LDD      100            // f32 D staging [128][100] = 51200 B at offset 0

// ---------------------------------------------------------------------------
// Device-global scratch
// ---------------------------------------------------------------------------
__device__ __align__(16) float g_NmatF[3600];
__device__ __align__(16) float g_W2T[15][96];
__device__ __align__(16) float g_coef2[96][3][26];
__device__ float g_cb[96];
__device__ float g_ob[96];
__device__ __align__(16) __half g_Wh[5][96][104];
__device__ __align__(16) __half g_Ah[NB][EMB][TVA];
__device__ __align__(16) __half g_Bh[NB][EMB][TVB2];

// ---------------------------------------------------------------------------
// helpers
// ---------------------------------------------------------------------------
__device__ __forceinline__ unsigned long long pack2(float a, float b) {
    unsigned long long r;
    asm("mov.b64 %0, {%1, %2};" : "=l"(r) : "f"(a), "f"(b));
    return r;
}
__device__ __forceinline__ void unpack2(unsigned long long v, float& lo, float& hi) {
    asm("mov.b64 {%0, %1}, %2;" : "=f"(lo), "=f"(hi) : "l"(v));
}
__device__ __forceinline__ void fma2(unsigned long long& acc,
                                     unsigned long long a, unsigned long long b) {
    asm("fma.rn.f32x2 %0, %1, %2, %0;" : "+l"(acc) : "l"(a), "l"(b));
}
__device__ __forceinline__ uint32_t h2_u32(__half2 h) {
    return *reinterpret_cast<uint32_t*>(&h);
}
__device__ __forceinline__ __half2 u32_h2(uint32_t u) {
    return *reinterpret_cast<__half2*>(&u);
}

// ---------------------------------------------------------------------------
// Setup (unchanged from R13)
// ---------------------------------------------------------------------------
__global__ __launch_bounds__(256) void kSetup(
                       const float* __restrict__ mlp_w, const float* __restrict__ mlp_b,
                       const float* __restrict__ g1, const float* __restrict__ b1,
                       const float* __restrict__ m1, const float* __restrict__ v1,
                       const float* __restrict__ out_w, const float* __restrict__ out_b,
                       const float* __restrict__ g2, const float* __restrict__ b2,
                       const float* __restrict__ m2, const float* __restrict__ v2)
{
    __shared__ unsigned int Brow[25];
    __shared__ unsigned int Sm[6][25];
    __shared__ float alph[6][25];
    __shared__ float alph2[6][25];
    int tid = threadIdx.x;
    int bid = blockIdx.x;

    if (tid < 25) {
        const unsigned char eg[24][2] = {{1,2},{2,21},{3,21},{4,3},{5,21},{6,5},
            {7,6},{8,7},{9,21},{10,9},{11,10},{12,11},{13,1},{14,13},{15,14},
            {16,15},{17,1},{18,17},{19,18},{20,19},{22,23},{23,8},{24,25},{25,12}};
        unsigned int m = 1u << tid;
        #pragma unroll
        for (int k = 0; k < 24; k++) {
            int a = eg[k][0] - 1, b = eg[k][1] - 1;
            if (a == tid) m |= 1u << b;
            if (b == tid) m |= 1u << a;
        }
        Brow[tid] = m;
        Sm[1][tid] = m;
    }
    __syncthreads();
    for (int k = 2; k <= 5; k++) {
        if (tid < 25) {
            unsigned int prev = Sm[k-1][tid], nm = prev;
            for (int u = 0; u < 25; u++)
                if ((prev >> u) & 1) nm |= Brow[u];
            Sm[k][tid] = nm;
        }
        __syncthreads();
    }
    if (tid < 125) {
        int s = tid / 25 + 1, v = tid % 25;
        int r = __popc(Sm[s][v]) - ((s >= 2) ? __popc(Sm[s-1][v]) : 0);
        int deg = 5 * r + ((s == 1) ? 0 : 1);
        alph[s][v]  = (deg > 0) ? 1.0f / sqrtf((float)deg) : 0.f;
        alph2[s][v] = (deg > 0) ? 1.0f / (float)deg : 0.f;
    }
    __syncthreads();

    if (bid == 0) {
        for (int i = tid; i < 3600; i += 256) {
            float val = 0.f;
            if (i < 3500) {
                int s0 = i / 700, r = i % 700, v = r / 28, u = r % 28;
                if (u < 25) {
                    unsigned int bits = Sm[s0+1][v] & ~((s0 >= 1) ? Sm[s0][v] : 0u);
                    val = ((bits >> u) & 1) ? alph[s0+1][v] * alph[s0+1][u] : 0.f;
                }
            }
            g_NmatF[i] = val;
        }
        for (int i = tid; i < 96 * 15; i += 256) {
            int e = i / 15, sc = i % 15;
            int s = sc / 3, c = sc % 3;
            float inv = g1[e] / sqrtf(v1[e] + 1e-5f);
            g_W2T[sc][e] = inv * mlp_w[e*18 + (s+1)*3 + c];
        }
        if (tid < 96) {
            float inv1 = g1[tid] / sqrtf(v1[tid] + 1e-5f);
            float inv2 = g2[tid] / sqrtf(v2[tid] + 1e-5f);
            g_cb[tid] = mlp_b[tid] * inv1 + b1[tid] - m1[tid] * inv1;
            g_ob[tid] = out_b[tid] * inv2 + b2[tid] - m2[tid] * inv2;
        }
        for (int i = tid; i < 96 * 3 * 26; i += 256) {
            int e = i / 78, c = (i / 26) % 3, v = i % 26;
            float val = 0.f;
            if (v < 25) {
                float acc = mlp_w[e*18 + c];
                #pragma unroll
                for (int s = 2; s <= 5; s++)
                    acc += alph2[s][v] * mlp_w[e*18 + s*3 + c];
                float inv = g1[e] / sqrtf(v1[e] + 1e-5f);
                val = inv * acc;
            }
            g_coef2[e][c][v] = val;
        }
    }

    for (int i = bid * 256 + tid; i < 5 * 96 * 104; i += 8 * 256) {
        int w = i / (96 * 104);
        int q = i % (96 * 104);
        int o = q / 104, k = q % 104;
        float val = 0.f;
        if (k < 96) {
            float inv2 = g2[o] / sqrtf(v2[o] + 1e-5f);
            val = inv2 * out_w[(o * 96 + k) * 5 + w];
        }
        g_Wh[w][o][k] = __float2half_rn(val);
    }
}

// ---------------------------------------------------------------------------
// A/B producer (unchanged from R13)
// ---------------------------------------------------------------------------
__global__ __launch_bounds__(256) void kAB(const float* __restrict__ x)
{
    __shared__ __align__(16) float S[9864];
    float* NsS  = S;
    float* W2s  = S + 3600;
    float* msS  = S + 5040;
    float* XsS  = S + 8160;
    float* xrS  = S + 8832;
    float* cbs  = S + 9768;

    int n  = blockIdx.y;
    int f0 = blockIdx.x * 8;
    int tid = threadIdx.x;

    {
        const float4* src = (const float4*)g_NmatF;
        float4* dst = (float4*)NsS;
        for (int i = tid; i < 900; i += 256) dst[i] = src[i];
        const float4* src2 = (const float4*)&g_W2T[0][0];
        float4* dst2 = (float4*)W2s;
        for (int i = tid; i < 360; i += 256) dst2[i] = src2[i];
    }
    if (tid < 96) cbs[tid] = g_cb[tid];
    for (int i = tid; i < 936; i += 256) {
        int c = i / 312, r = i - c * 312;
        int fr = r / 26, v = r - fr * 26;
        int tau = f0 - 4 + fr;
        float val = 0.f;
        if (tau >= 0 && tau < TT && v < 25)
            val = x[((n*3 + c)*TT + tau)*VV + v];
        xrS[i] = val;
    }
    __syncthreads();

    for (int i = tid; i < 672; i += 256) {
        int c = i / 224, r = i - c * 224;
        int j = r / 28, u = r - j * 28;
        float s = 0.f;
        if (u < 25) {
            const float* xp = &xrS[(c*12 + j)*26 + u];
            s = xp[0] + xp[26] + xp[52] + xp[78] + xp[104];
        }
        XsS[i] = s;
    }
    __syncthreads();

    for (int i = tid; i < 3120; i += 256) {
        int sc = i / 208, col = i - sc * 208;
        int s = sc / 3, c = sc - s * 3;
        int j = col / 26, v = col - j * 26;
        float acc = 0.f;
        if (v < 25) {
            const float* Nrow = &NsS[(s*25 + v)*28];
            const float* Xr = &XsS[(c*8 + j)*28];
            #pragma unroll
            for (int q = 0; q < 7; q++) {
                float4 nv = *(const float4*)(Nrow + q*4);
                float4 xv = *(const float4*)(Xr + q*4);
                acc += nv.x*xv.x + nv.y*xv.y + nv.z*xv.z + nv.w*xv.w;
            }
        }
        msS[i] = acc;
    }
    __syncthreads();

    int og = tid >> 5;
    int cg = tid & 31;
    for (int h = 0; h < 2; h++) {
        if (cg < 26) {
            unsigned long long acc[6][4];
            #pragma unroll
            for (int p = 0; p < 6; p++)
                #pragma unroll
                for (int j = 0; j < 4; j++) acc[p][j] = 0ULL;

            int colb = cg << 2;
            #pragma unroll
            for (int sc = 0; sc < 15; sc++) {
                float4 m4 = *(const float4*)&msS[sc*208 + h*104 + colb];
                unsigned long long hh0 = pack2(m4.x, m4.x);
                unsigned long long hh1 = pack2(m4.y, m4.y);
                unsigned long long hh2 = pack2(m4.z, m4.z);
                unsigned long long hh3 = pack2(m4.w, m4.w);
                const ulonglong2* wp = (const ulonglong2*)&W2s[sc*96 + og*12];
                ulonglong2 wa = wp[0], wb = wp[1], wc = wp[2];
                fma2(acc[0][0], wa.x, hh0); fma2(acc[0][1], wa.x, hh1);
                fma2(acc[0][2], wa.x, hh2); fma2(acc[0][3], wa.x, hh3);
                fma2(acc[1][0], wa.y, hh0); fma2(acc[1][1], wa.y, hh1);
                fma2(acc[1][2], wa.y, hh2); fma2(acc[1][3], wa.y, hh3);
                fma2(acc[2][0], wb.x, hh0); fma2(acc[2][1], wb.x, hh1);
                fma2(acc[2][2], wb.x, hh2); fma2(acc[2][3], wb.x, hh3);
                fma2(acc[3][0], wb.y, hh0); fma2(acc[3][1], wb.y, hh1);
                fma2(acc[3][2], wb.y, hh2); fma2(acc[3][3], wb.y, hh3);
                fma2(acc[4][0], wc.x, hh0); fma2(acc[4][1], wc.x, hh1);
                fma2(acc[4][2], wc.x, hh2); fma2(acc[4][3], wc.x, hh3);
                fma2(acc[5][0], wc.y, hh0); fma2(acc[5][1], wc.y, hh1);
                fma2(acc[5][2], wc.y, hh2); fma2(acc[5][3], wc.y, hh3);
            }

            int t0 = f0 - 2 + 4*h;
            int lo = (t0 < 0) ? (-t0) * PC : 0;
            int hi = ((TT - t0) < 4 ? (TT - t0) : 4) * PC;
            if (colb >= lo && colb + 4 <= hi) {
                long gc = (long)t0 * PC + colb;
                #pragma unroll
                for (int p = 0; p < 6; p++) {
                    int o = og * 12 + 2 * p;
                    float blo = cbs[o], bhi = cbs[o + 1];
                    float l0,h0_,l1,h1_,l2,h2_,l3,h3_;
                    unpack2(acc[p][0], l0, h0_);
                    unpack2(acc[p][1], l1, h1_);
                    unpack2(acc[p][2], l2, h2_);
                    unpack2(acc[p][3], l3, h3_);
                    __half2 a01 = __floats2half2_rn(l0+blo, l1+blo);
                    __half2 a23 = __floats2half2_rn(l2+blo, l3+blo);
                    __half2 b01 = __floats2half2_rn(h0_+bhi, h1_+bhi);
                    __half2 b23 = __floats2half2_rn(h2_+bhi, h3_+bhi);
                    *(uint2*)&g_Ah[n][o][gc]   = make_uint2(h2_u32(a01), h2_u32(a23));
                    *(uint2*)&g_Ah[n][o+1][gc] = make_uint2(h2_u32(b01), h2_u32(b23));
                }
            }
        }
    }

    for (int i = tid; i < 96 * 13; i += 256) {
        int e = i / 13, vp = i - e * 13;
        int v = vp << 1;
        float2 c0 = *(const float2*)&g_coef2[e][0][v];
        float2 c1 = *(const float2*)&g_coef2[e][1][v];
        float2 c2 = *(const float2*)&g_coef2[e][2][v];
        unsigned long long cc0 = pack2(c0.x, c0.y);
        unsigned long long cc1 = pack2(c1.x, c1.y);
        unsigned long long cc2 = pack2(c2.x, c2.y);
        __half* Bo = &g_Bh[n][e][(long)f0 * PC + v];
        #pragma unroll
        for (int j = 0; j < 8; j++) {
            float2 x0 = *(const float2*)&xrS[((0*12) + j+2)*26 + v];
            float2 x1 = *(const float2*)&xrS[((1*12) + j+2)*26 + v];
            float2 x2 = *(const float2*)&xrS[((2*12) + j+2)*26 + v];
            unsigned long long acc = 0ULL;
            fma2(acc, cc0, pack2(x0.x, x0.y));
            fma2(acc, cc1, pack2(x1.x, x1.y));
            fma2(acc, cc2, pack2(x2.x, x2.y));
            float lo, hi;
            unpack2(acc, lo, hi);
            *(uint32_t*)(Bo + j * PC) = h2_u32(__floats2half2_rn(lo, hi));
        }
    }
}

// ---------------------------------------------------------------------------
// Output GEMM: warp-specialized WMMA fp16.
// Warps 0-5: MMA consumers (tile 64x32, acc[4][2]).
// Warps 6-7: producers — build H(w+1) + prefetch W(w+1) while MMA(w) runs.
// Double-buffered H and W; one __syncthreads per w. 1 CTA/SM (159 KB smem).
// ---------------------------------------------------------------------------
__global__ __launch_bounds__(256, 1) void kOutTC(float* __restrict__ out)
{
    extern __shared__ char smem[];
    __half* As = (__half*)(smem + OFF_A);
    __half* Hbuf[2] = { (__half*)(smem + OFF_H0), (__half*)(smem + OFF_H1) };
    __half* Bs = (__half*)(smem + OFF_B);
    __half* Wbuf[2] = { (__half*)(smem + OFF_W0), (__half*)(smem + OFF_W1) };
    float* obs = (float*)(smem + OFF_OBS);

    int tid = threadIdx.x;
    int n = blockIdx.y;
    int col0 = blockIdx.x * 128;
    int wid = tid >> 5;

    if (tid < 96) obs[tid] = g_ob[tid];

    // stage B tile: rows e=0..95, cols [col0, col0+232)
    for (int i = tid; i < 96 * 29; i += 256) {
        int e = i / 29, q = i - e * 29;
        *(uint4*)(Bs + e * LDBS + q * 8) =
            *(const uint4*)(&g_Bh[n][e][col0 + q * 8]);
    }
    // stage A tile (zero beyond TVA)
    #pragma unroll
    for (int k = 0; k < 12; k++) {
        int i = tid + k * 256;
        int e = i >> 5, c4 = (i & 31) << 2;
        int tv = col0 + c4;
        uint2 a = (tv < TVA) ? *(const uint2*)(&g_Ah[n][e][tv])
                             : make_uint2(0u, 0u);
        *(uint2*)(As + e * LDA + c4) = a;
    }
    // stage W(0)
    {
        const uint4* src = (const uint4*)(&g_Wh[0][0][0]);
        uint4* dst = (uint4*)Wbuf[0];
        for (int i = tid; i < 1248; i += 256) dst[i] = src[i];
    }
    __syncthreads();

    const __half2 z2 = __floats2half2_rn(0.f, 0.f);

    // build H(0) (all warps)
    #pragma unroll
    for (int k = 0; k < 12; k++) {
        int i = tid + k * 256;
        int e = i >> 5, c4 = (i & 31) << 2;
        uint2 a = *(const uint2*)(As + e * LDA + c4);
        const __half* bp = Bs + e * LDBS + c4;
        __half2 h01 = __hmax2(__hadd2(u32_h2(a.x), *(const __half2*)bp), z2);
        __half2 h23 = __hmax2(__hadd2(u32_h2(a.y), *(const __half2*)(bp + 2)), z2);
        *(uint2*)(Hbuf[0] + e * LDA + c4) = make_uint2(h2_u32(h01), h2_u32(h23));
    }
    __syncthreads();

    // consumer tiling: 2 M-halves x 3 N-groups
    int mw = wid & 1;              // 0/1 -> M offset 0/64
    int nw = wid >> 1;             // 0..2 -> N offset 0/32/64 (consumers only)
    int m0 = mw * 64;
    int n0 = nw * 32;

    wmma::fragment<wmma::accumulator, 16, 16, 16, float> acc[4][2];
    if (wid < 6) {
        #pragma unroll
        for (int i = 0; i < 4; i++)
            #pragma unroll
            for (int j = 0; j < 2; j++)
                wmma::fill_fragment(acc[i][j], 0.0f);
    }

    for (int w = 0; w < 5; w++) {
        if (wid < 6) {
            // ---- consumers: MMA(w) ----
            const __half* Hcur = Hbuf[w & 1];
            const __half* Wcur = Wbuf[w & 1];
            #pragma unroll
            for (int kf = 0; kf < 6; kf++) {
                int k0 = kf * 16;
                wmma::fragment<wmma::matrix_b, 16, 16, 16, __half,
                               wmma::col_major> bf[2];
                #pragma unroll
                for (int j = 0; j < 2; j++)
                    wmma::load_matrix_sync(bf[j], Wcur + (n0 + 16 * j) * 104 + k0, 104);
                #pragma unroll
                for (int i = 0; i < 4; i++) {
                    wmma::fragment<wmma::matrix_a, 16, 16, 16, __half,
                                   wmma::col_major> af;
                    wmma::load_matrix_sync(af, Hcur + k0 * LDA + m0 + 16 * i, LDA);
                    #pragma unroll
                    for (int j = 0; j < 2; j++)
                        wmma::mma_sync(acc[i][j], af, bf[j], acc[i][j]);
                }
            }
        } else if (w < 4) {
            // ---- producers: build H(w+1), prefetch W(w+1) ----
            int ptid = tid - 192;      // 0..63
            __half* Hnext = Hbuf[(w + 1) & 1];
            int boff = PC * (w + 1);
            #pragma unroll
            for (int k = 0; k < 48; k++) {
                int i = ptid + k * 64;
                int e = i >> 5, c4 = (i & 31) << 2;
                uint2 a = *(const uint2*)(As + e * LDA + c4);
                const __half* bp = Bs + e * LDBS + c4 + boff;
                __half2 h01 = __hmax2(__hadd2(u32_h2(a.x), *(const __half2*)bp), z2);
                __half2 h23 = __hmax2(__hadd2(u32_h2(a.y), *(const __half2*)(bp + 2)), z2);
                *(uint2*)(Hnext + e * LDA + c4) = make_uint2(h2_u32(h01), h2_u32(h23));
            }
            const uint4* src = (const uint4*)(&g_Wh[w + 1][0][0]);
            uint4* dst = (uint4*)Wbuf[(w + 1) & 1];
            for (int i = ptid; i < 1248; i += 64) dst[i] = src[i];
        }
        __syncthreads();
    }

    // epilogue: consumers stage D to smem (reuses As/H0 bytes), all warps write
    float* Ds = (float*)smem;
    if (wid < 6) {
        #pragma unroll
        for (int i = 0; i < 4; i++)
            #pragma unroll
            for (int j = 0; j < 2; j++)
                wmma::store_matrix_sync(Ds + (m0 + 16 * i) * LDD + (n0 + 16 * j),
                                        acc[i][j], LDD, wmma::mem_row_major);
    }
    __syncthreads();

    for (int q = tid; q < 96 * 128; q += 256) {
        int o = q >> 7, col = q & 127;
        int tv = col0 + col;
        int t = tv / PC, v = tv - t * PC;
        if (tv < TVA && v < VV) {
            out[((size_t)(n * 96 + o)) * OUTTV + t * VV + v] =
                Ds[col * LDD + o] + obs[o];
        }
    }
}

// ---------------------------------------------------------------------------
// Launcher
// ---------------------------------------------------------------------------
extern "C" void kernel_launch(void* const* d_in, const int* in_sizes, int n_in,
                              void* d_out, int out_size)
{
    (void)in_sizes; (void)n_in; (void)out_size;
    const float* x     = (const float*)d_in[0];
    const float* mlp_w = (const float*)d_in[1];
    const float* mlp_b = (const float*)d_in[2];
    const float* g1    = (const float*)d_in[3];
    const float* b1    = (const float*)d_in[4];
    const float* m1    = (const float*)d_in[5];
    const float* v1    = (const float*)d_in[6];
    const float* out_w = (const float*)d_in[7];
    const float* out_b = (const float*)d_in[8];
    const float* g2    = (const float*)d_in[9];
    const float* b2    = (const float*)d_in[10];
    const float* m2    = (const float*)d_in[11];
    const float* v2    = (const float*)d_in[12];
    float* out = (float*)d_out;

    cudaFuncSetAttribute(kOutTC, cudaFuncAttributeMaxDynamicSharedMemorySize, SMEM_TC);

    kSetup<<<8, 256>>>(mlp_w, mlp_b, g1, b1, m1, v1, out_w, out_b, g2, b2, m2, v2);
    kAB<<<dim3(NFB / 8, NB), 256>>>(x);
    kOutTC<<<dim3((TVA + 127) / 128, NB), 256, SMEM_TC>>>(out);
}

// round 16
// speedup vs baseline: 2.4362x; 2.4362x over previous
#include <cuda_runtime.h>
#include <cuda_bf16.h>
#include <cuda_fp16.h>
#include <mma.h>
#include <math.h>
#include <stdint.h>

using namespace nvcuda;

// ---------------------------------------------------------------------------
// Problem constants
// ---------------------------------------------------------------------------
#define NB   64
#define TT   300
#define VV   25
#define PC   26                 // padded cols per frame
#define EMB  96
#define TVA  (TT*PC)            // 7800
#define NFB  (TT+4)             // 304
#define TVB2 7912               // B row stride (halves), pad for uint4 tile loads
#define OUTTV (TT*VV)           // 7500

// smem layout for kOutTC (bytes)  — R13 layout
#define LDA      136
#define LDBS     232            // B tile width in halves (128 + 4*26)
#define OFF_H    0              // [96][136] fp16 = 26112
#define OFF_B    26112          // [96][232] fp16 = 44544
#define OFF_W    70656          // [96][104] fp16 = 19968
#define OFF_OBS  90624          // [96] f32 = 384
#define SMEM_TC  91008
#define LDD      100            // f32 D staging [128][100] = 51200 B at offset 0

// ---------------------------------------------------------------------------
// Device-global scratch
// ---------------------------------------------------------------------------
__device__ __align__(16) float g_NmatF[3600];        // [s][v][28] padded rows
__device__ __align__(16) float g_W2T[15][96];
__device__ __align__(16) float g_coef2[96][3][26];
__device__ float g_cb[96];
__device__ float g_ob[96];
__device__ __align__(16) __half g_Wh[5][96][104];    // [w][o][k=e] fp16 B tiles
__device__ __align__(16) __half g_Ah[NB][EMB][TVA];  // A + cb, fp16
__device__ __align__(16) __half g_Bh[NB][EMB][TVB2]; // B, fp16, frame-haloed

// ---------------------------------------------------------------------------
// helpers
// ---------------------------------------------------------------------------
__device__ __forceinline__ unsigned long long pack2(float a, float b) {
    unsigned long long r;
    asm("mov.b64 %0, {%1, %2};" : "=l"(r) : "f"(a), "f"(b));
    return r;
}
__device__ __forceinline__ void unpack2(unsigned long long v, float& lo, float& hi) {
    asm("mov.b64 {%0, %1}, %2;" : "=f"(lo), "=f"(hi) : "l"(v));
}
__device__ __forceinline__ void fma2(unsigned long long& acc,
                                     unsigned long long a, unsigned long long b) {
    asm("fma.rn.f32x2 %0, %1, %2, %0;" : "+l"(acc) : "l"(a), "l"(b));
}
__device__ __forceinline__ uint32_t h2_u32(__half2 h) {
    return *reinterpret_cast<uint32_t*>(&h);
}
__device__ __forceinline__ __half2 u32_h2(uint32_t u) {
    return *reinterpret_cast<__half2*>(&u);
}

// ---------------------------------------------------------------------------
// Setup (unchanged from R13)
// ---------------------------------------------------------------------------
__global__ __launch_bounds__(256) void kSetup(
                       const float* __restrict__ mlp_w, const float* __restrict__ mlp_b,
                       const float* __restrict__ g1, const float* __restrict__ b1,
                       const float* __restrict__ m1, const float* __restrict__ v1,
                       const float* __restrict__ out_w, const float* __restrict__ out_b,
                       const float* __restrict__ g2, const float* __restrict__ b2,
                       const float* __restrict__ m2, const float* __restrict__ v2)
{
    __shared__ unsigned int Brow[25];
    __shared__ unsigned int Sm[6][25];
    __shared__ float alph[6][25];
    __shared__ float alph2[6][25];
    int tid = threadIdx.x;
    int bid = blockIdx.x;

    if (tid < 25) {
        const unsigned char eg[24][2] = {{1,2},{2,21},{3,21},{4,3},{5,21},{6,5},
            {7,6},{8,7},{9,21},{10,9},{11,10},{12,11},{13,1},{14,13},{15,14},
            {16,15},{17,1},{18,17},{19,18},{20,19},{22,23},{23,8},{24,25},{25,12}};
        unsigned int m = 1u << tid;
        #pragma unroll
        for (int k = 0; k < 24; k++) {
            int a = eg[k][0] - 1, b = eg[k][1] - 1;
            if (a == tid) m |= 1u << b;
            if (b == tid) m |= 1u << a;
        }
        Brow[tid] = m;
        Sm[1][tid] = m;
    }
    __syncthreads();
    for (int k = 2; k <= 5; k++) {
        if (tid < 25) {
            unsigned int prev = Sm[k-1][tid], nm = prev;
            for (int u = 0; u < 25; u++)
                if ((prev >> u) & 1) nm |= Brow[u];
            Sm[k][tid] = nm;
        }
        __syncthreads();
    }
    if (tid < 125) {
        int s = tid / 25 + 1, v = tid % 25;
        int r = __popc(Sm[s][v]) - ((s >= 2) ? __popc(Sm[s-1][v]) : 0);
        int deg = 5 * r + ((s == 1) ? 0 : 1);
        alph[s][v]  = (deg > 0) ? 1.0f / sqrtf((float)deg) : 0.f;
        alph2[s][v] = (deg > 0) ? 1.0f / (float)deg : 0.f;
    }
    __syncthreads();

    if (bid == 0) {
        for (int i = tid; i < 3600; i += 256) {
            float val = 0.f;
            if (i < 3500) {
                int s0 = i / 700, r = i % 700, v = r / 28, u = r % 28;
                if (u < 25) {
                    unsigned int bits = Sm[s0+1][v] & ~((s0 >= 1) ? Sm[s0][v] : 0u);
                    val = ((bits >> u) & 1) ? alph[s0+1][v] * alph[s0+1][u] : 0.f;
                }
            }
            g_NmatF[i] = val;
        }
        for (int i = tid; i < 96 * 15; i += 256) {
            int e = i / 15, sc = i % 15;
            int s = sc / 3, c = sc % 3;
            float inv = g1[e] / sqrtf(v1[e] + 1e-5f);
            g_W2T[sc][e] = inv * mlp_w[e*18 + (s+1)*3 + c];
        }
        if (tid < 96) {
            float inv1 = g1[tid] / sqrtf(v1[tid] + 1e-5f);
            float inv2 = g2[tid] / sqrtf(v2[tid] + 1e-5f);
            g_cb[tid] = mlp_b[tid] * inv1 + b1[tid] - m1[tid] * inv1;
            g_ob[tid] = out_b[tid] * inv2 + b2[tid] - m2[tid] * inv2;
        }
        for (int i = tid; i < 96 * 3 * 26; i += 256) {
            int e = i / 78, c = (i / 26) % 3, v = i % 26;
            float val = 0.f;
            if (v < 25) {
                float acc = mlp_w[e*18 + c];
                #pragma unroll
                for (int s = 2; s <= 5; s++)
                    acc += alph2[s][v] * mlp_w[e*18 + s*3 + c];
                float inv = g1[e] / sqrtf(v1[e] + 1e-5f);
                val = inv * acc;
            }
            g_coef2[e][c][v] = val;
        }
    }

    // fp16 output weights as col-major B tiles: g_Wh[w][o][k=e]
    for (int i = bid * 256 + tid; i < 5 * 96 * 104; i += 8 * 256) {
        int w = i / (96 * 104);
        int q = i % (96 * 104);
        int o = q / 104, k = q % 104;
        float val = 0.f;
        if (k < 96) {
            float inv2 = g2[o] / sqrtf(v2[o] + 1e-5f);
            val = inv2 * out_w[(o * 96 + k) * 5 + w];
        }
        g_Wh[w][o][k] = __float2half_rn(val);
    }
}

// ---------------------------------------------------------------------------
// A/B producer: R13 structure; ms loop restructured so the N-row is cached
// in registers and reused across all 8 frames (LDS traffic -44%).
// ---------------------------------------------------------------------------
__global__ __launch_bounds__(256) void kAB(const float* __restrict__ x)
{
    __shared__ __align__(16) float S[9864];
    float* NsS  = S;                // [3600]  = [s][v][28]
    float* W2s  = S + 3600;         // [15][96]
    float* msS  = S + 5040;         // [15][208]
    float* XsS  = S + 8160;         // [3][8][28]
    float* xrS  = S + 8832;         // [3][12][26]
    float* cbs  = S + 9768;         // [96]

    int n  = blockIdx.y;
    int f0 = blockIdx.x * 8;
    int tid = threadIdx.x;

    {
        const float4* src = (const float4*)g_NmatF;
        float4* dst = (float4*)NsS;
        for (int i = tid; i < 900; i += 256) dst[i] = src[i];
        const float4* src2 = (const float4*)&g_W2T[0][0];
        float4* dst2 = (float4*)W2s;
        for (int i = tid; i < 360; i += 256) dst2[i] = src2[i];
    }
    if (tid < 96) cbs[tid] = g_cb[tid];
    for (int i = tid; i < 936; i += 256) {
        int c = i / 312, r = i - c * 312;
        int fr = r / 26, v = r - fr * 26;
        int tau = f0 - 4 + fr;
        float val = 0.f;
        if (tau >= 0 && tau < TT && v < 25)
            val = x[((n*3 + c)*TT + tau)*VV + v];
        xrS[i] = val;
    }
    __syncthreads();

    for (int i = tid; i < 672; i += 256) {
        int c = i / 224, r = i - c * 224;
        int j = r / 28, u = r - j * 28;
        float s = 0.f;
        if (u < 25) {
            const float* xp = &xrS[(c*12 + j)*26 + u];
            s = xp[0] + xp[26] + xp[52] + xp[78] + xp[104];
        }
        XsS[i] = s;
    }
    __syncthreads();

    // ms[sc][j*26+v] : one thread per (sc,v), N-row cached, 8 frames reused
    for (int i = tid; i < 390; i += 256) {
        int sc = i / 26, v = i - sc * 26;
        int s = sc / 3, c = sc - s * 3;
        if (v < 25) {
            const float* Nrow = &NsS[(s*25 + v)*28];
            float4 n0 = *(const float4*)(Nrow);
            float4 n1 = *(const float4*)(Nrow + 4);
            float4 n2 = *(const float4*)(Nrow + 8);
            float4 n3 = *(const float4*)(Nrow + 12);
            float4 n4 = *(const float4*)(Nrow + 16);
            float4 n5 = *(const float4*)(Nrow + 20);
            float4 n6 = *(const float4*)(Nrow + 24);
            #pragma unroll
            for (int j = 0; j < 8; j++) {
                const float* Xr = &XsS[(c*8 + j)*28];
                float4 x0 = *(const float4*)(Xr);
                float4 x1 = *(const float4*)(Xr + 4);
                float4 x2 = *(const float4*)(Xr + 8);
                float4 x3 = *(const float4*)(Xr + 12);
                float4 x4 = *(const float4*)(Xr + 16);
                float4 x5 = *(const float4*)(Xr + 20);
                float4 x6 = *(const float4*)(Xr + 24);
                float acc =
                    n0.x*x0.x + n0.y*x0.y + n0.z*x0.z + n0.w*x0.w +
                    n1.x*x1.x + n1.y*x1.y + n1.z*x1.z + n1.w*x1.w +
                    n2.x*x2.x + n2.y*x2.y + n2.z*x2.z + n2.w*x2.w +
                    n3.x*x3.x + n3.y*x3.y + n3.z*x3.z + n3.w*x3.w +
                    n4.x*x4.x + n4.y*x4.y + n4.z*x4.z + n4.w*x4.w +
                    n5.x*x5.x + n5.y*x5.y + n5.z*x5.z + n5.w*x5.w +
                    n6.x*x6.x + n6.y*x6.y + n6.z*x6.z + n6.w*x6.w;
                msS[sc*208 + j*26 + v] = acc;
            }
        } else {
            #pragma unroll
            for (int j = 0; j < 8; j++)
                msS[sc*208 + j*26 + v] = 0.f;
        }
    }
    __syncthreads();

    int og = tid >> 5;
    int cg = tid & 31;
    for (int h = 0; h < 2; h++) {
        if (cg < 26) {
            unsigned long long acc[6][4];
            #pragma unroll
            for (int p = 0; p < 6; p++)
                #pragma unroll
                for (int j = 0; j < 4; j++) acc[p][j] = 0ULL;

            int colb = cg << 2;
            #pragma unroll
            for (int sc = 0; sc < 15; sc++) {
                float4 m4 = *(const float4*)&msS[sc*208 + h*104 + colb];
                unsigned long long hh0 = pack2(m4.x, m4.x);
                unsigned long long hh1 = pack2(m4.y, m4.y);
                unsigned long long hh2 = pack2(m4.z, m4.z);
                unsigned long long hh3 = pack2(m4.w, m4.w);
                const ulonglong2* wp = (const ulonglong2*)&W2s[sc*96 + og*12];
                ulonglong2 wa = wp[0], wb = wp[1], wc = wp[2];
                fma2(acc[0][0], wa.x, hh0); fma2(acc[0][1], wa.x, hh1);
                fma2(acc[0][2], wa.x, hh2); fma2(acc[0][3], wa.x, hh3);
                fma2(acc[1][0], wa.y, hh0); fma2(acc[1][1], wa.y, hh1);
                fma2(acc[1][2], wa.y, hh2); fma2(acc[1][3], wa.y, hh3);
                fma2(acc[2][0], wb.x, hh0); fma2(acc[2][1], wb.x, hh1);
                fma2(acc[2][2], wb.x, hh2); fma2(acc[2][3], wb.x, hh3);
                fma2(acc[3][0], wb.y, hh0); fma2(acc[3][1], wb.y, hh1);
                fma2(acc[3][2], wb.y, hh2); fma2(acc[3][3], wb.y, hh3);
                fma2(acc[4][0], wc.x, hh0); fma2(acc[4][1], wc.x, hh1);
                fma2(acc[4][2], wc.x, hh2); fma2(acc[4][3], wc.x, hh3);
                fma2(acc[5][0], wc.y, hh0); fma2(acc[5][1], wc.y, hh1);
                fma2(acc[5][2], wc.y, hh2); fma2(acc[5][3], wc.y, hh3);
            }

            int t0 = f0 - 2 + 4*h;
            int lo = (t0 < 0) ? (-t0) * PC : 0;
            int hi = ((TT - t0) < 4 ? (TT - t0) : 4) * PC;
            if (colb >= lo && colb + 4 <= hi) {
                long gc = (long)t0 * PC + colb;
                #pragma unroll
                for (int p = 0; p < 6; p++) {
                    int o = og * 12 + 2 * p;
                    float blo = cbs[o], bhi = cbs[o + 1];
                    float l0,h0_,l1,h1_,l2,h2_,l3,h3_;
                    unpack2(acc[p][0], l0, h0_);
                    unpack2(acc[p][1], l1, h1_);
                    unpack2(acc[p][2], l2, h2_);
                    unpack2(acc[p][3], l3, h3_);
                    __half2 a01 = __floats2half2_rn(l0+blo, l1+blo);
                    __half2 a23 = __floats2half2_rn(l2+blo, l3+blo);
                    __half2 b01 = __floats2half2_rn(h0_+bhi, h1_+bhi);
                    __half2 b23 = __floats2half2_rn(h2_+bhi, h3_+bhi);
                    *(uint2*)&g_Ah[n][o][gc]   = make_uint2(h2_u32(a01), h2_u32(a23));
                    *(uint2*)&g_Ah[n][o+1][gc] = make_uint2(h2_u32(b01), h2_u32(b23));
                }
            }
        }
    }

    for (int i = tid; i < 96 * 13; i += 256) {
        int e = i / 13, vp = i - e * 13;
        int v = vp << 1;
        float2 c0 = *(const float2*)&g_coef2[e][0][v];
        float2 c1 = *(const float2*)&g_coef2[e][1][v];
        float2 c2 = *(const float2*)&g_coef2[e][2][v];
        unsigned long long cc0 = pack2(c0.x, c0.y);
        unsigned long long cc1 = pack2(c1.x, c1.y);
        unsigned long long cc2 = pack2(c2.x, c2.y);
        __half* Bo = &g_Bh[n][e][(long)f0 * PC + v];
        #pragma unroll
        for (int j = 0; j < 8; j++) {
            float2 x0 = *(const float2*)&xrS[((0*12) + j+2)*26 + v];
            float2 x1 = *(const float2*)&xrS[((1*12) + j+2)*26 + v];
            float2 x2 = *(const float2*)&xrS[((2*12) + j+2)*26 + v];
            unsigned long long acc = 0ULL;
            fma2(acc, cc0, pack2(x0.x, x0.y));
            fma2(acc, cc1, pack2(x1.x, x1.y));
            fma2(acc, cc2, pack2(x2.x, x2.y));
            float lo, hi;
            unpack2(acc, lo, hi);
            *(uint32_t*)(Bo + j * PC) = h2_u32(__floats2half2_rn(lo, hi));
        }
    }
}

// ---------------------------------------------------------------------------
// Output GEMM via WMMA fp16 (R13 exactly): read-once tiling + W staged in smem.
// ---------------------------------------------------------------------------
__global__ __launch_bounds__(256, 2) void kOutTC(float* __restrict__ out)
{
    extern __shared__ char smem[];
    __half* Hs = (__half*)(smem + OFF_H);
    __half* Bs = (__half*)(smem + OFF_B);
    __half* Ws = (__half*)(smem + OFF_W);
    float* obs = (float*)(smem + OFF_OBS);

    int tid = threadIdx.x;
    int n = blockIdx.y;
    int col0 = blockIdx.x * 128;
    int warpid = tid >> 5;
    int m0 = (warpid & 3) * 32;    // col offset of warp tile
    int n0 = (warpid >> 2) * 48;   // out offset of warp tile

    if (tid < 96) obs[tid] = g_ob[tid];

    // B tile: rows e=0..95, cols [col0, col0+232)
    for (int i = tid; i < 96 * 29; i += 256) {
        int e = i / 29, q = i - e * 29;
        *(uint4*)(Bs + e * LDBS + q * 8) =
            *(const uint4*)(&g_Bh[n][e][col0 + q * 8]);
    }

    // A tile into registers
    uint2 Areg[12];
    #pragma unroll
    for (int k = 0; k < 12; k++) {
        int i = tid + k * 256;
        int e = i >> 5, c4 = (i & 31) << 2;
        int tv = col0 + c4;
        Areg[k] = (tv < TVA) ? *(const uint2*)(&g_Ah[n][e][tv])
                             : make_uint2(0u, 0u);
    }

    wmma::fragment<wmma::accumulator, 16, 16, 16, float> acc[2][3];
    #pragma unroll
    for (int i = 0; i < 2; i++)
        #pragma unroll
        for (int j = 0; j < 3; j++)
            wmma::fill_fragment(acc[i][j], 0.0f);

    __syncthreads();

    const __half2 z2 = __floats2half2_rn(0.f, 0.f);
    bool edge = (col0 + 128 > TVA);

    for (int w = 0; w < 5; w++) {
        // build H = relu(A + B_shift) in fp16
        #pragma unroll
        for (int k = 0; k < 12; k++) {
            int i = tid + k * 256;
            int e = i >> 5, c4 = (i & 31) << 2;
            __half2 h01 = z2, h23 = z2;
            if (!edge || col0 + c4 < TVA) {
                __half2 a01 = u32_h2(Areg[k].x);
                __half2 a23 = u32_h2(Areg[k].y);
                const __half* bp = Bs + e * LDBS + c4 + PC * w;
                h01 = __hmax2(__hadd2(a01, *(const __half2*)bp), z2);
                h23 = __hmax2(__hadd2(a23, *(const __half2*)(bp + 2)), z2);
            }
            *(uint2*)(Hs + e * LDA + c4) = make_uint2(h2_u32(h01), h2_u32(h23));
        }
        // stage fp16 W tile for this w (19968 B = 1248 uint4)
        {
            const uint4* src = (const uint4*)(&g_Wh[w][0][0]);
            uint4* dst = (uint4*)Ws;
            #pragma unroll 5
            for (int i = tid; i < 1248; i += 256) dst[i] = src[i];
        }
        __syncthreads();

        #pragma unroll
        for (int kf = 0; kf < 6; kf++) {
            int k0 = kf * 16;
            wmma::fragment<wmma::matrix_b, 16, 16, 16, __half,
                           wmma::col_major> bf[3];
            #pragma unroll
            for (int j = 0; j < 3; j++)
                wmma::load_matrix_sync(bf[j], Ws + (n0 + 16 * j) * 104 + k0, 104);
            wmma::fragment<wmma::matrix_a, 16, 16, 16, __half,
                           wmma::col_major> af0, af1;
            wmma::load_matrix_sync(af0, Hs + k0 * LDA + m0, LDA);
            wmma::load_matrix_sync(af1, Hs + k0 * LDA + m0 + 16, LDA);
            #pragma unroll
            for (int j = 0; j < 3; j++) {
                wmma::mma_sync(acc[0][j], af0, bf[j], acc[0][j]);
                wmma::mma_sync(acc[1][j], af1, bf[j], acc[1][j]);
            }
        }
        __syncthreads();   // before next w overwrites H/W tiles
    }

    // epilogue: stage D to smem (reuses H/B bytes [0,51200)), compact write
    float* Ds = (float*)smem;
    #pragma unroll
    for (int i = 0; i < 2; i++)
        #pragma unroll
        for (int j = 0; j < 3; j++)
            wmma::store_matrix_sync(Ds + (m0 + 16 * i) * LDD + (n0 + 16 * j),
                                    acc[i][j], LDD, wmma::mem_row_major);
    __syncthreads();

    for (int q = tid; q < 96 * 128; q += 256) {
        int o = q >> 7, col = q & 127;
        int tv = col0 + col;
        int t = tv / PC, v = tv - t * PC;
        if (tv < TVA && v < VV) {
            out[((size_t)(n * 96 + o)) * OUTTV + t * VV + v] =
                Ds[col * LDD + o] + obs[o];
        }
    }
}

// ---------------------------------------------------------------------------
// Launcher
// ---------------------------------------------------------------------------
extern "C" void kernel_launch(void* const* d_in, const int* in_sizes, int n_in,
                              void* d_out, int out_size)
{
    (void)in_sizes; (void)n_in; (void)out_size;
    const float* x     = (const float*)d_in[0];
    const float* mlp_w = (const float*)d_in[1];
    const float* mlp_b = (const float*)d_in[2];
    const float* g1    = (const float*)d_in[3];
    const float* b1    = (const float*)d_in[4];
    const float* m1    = (const float*)d_in[5];
    const float* v1    = (const float*)d_in[6];
    const float* out_w = (const float*)d_in[7];
    const float* out_b = (const float*)d_in[8];
    const float* g2    = (const float*)d_in[9];
    const float* b2    = (const float*)d_in[10];
    const float* m2    = (const float*)d_in[11];
    const float* v2    = (const float*)d_in[12];
    float* out = (float*)d_out;

    cudaFuncSetAttribute(kOutTC, cudaFuncAttributeMaxDynamicSharedMemorySize, SMEM_TC);

    kSetup<<<8, 256>>>(mlp_w, mlp_b, g1, b1, m1, v1, out_w, out_b, g2, b2, m2, v2);
    kAB<<<dim3(NFB / 8, NB), 256>>>(x);
    kOutTC<<<dim3((TVA + 127) / 128, NB), 256, SMEM_TC>>>(out);
}